// round 2
// baseline (speedup 1.0000x reference)
#include <cuda_runtime.h>
#include <math.h>
#include <float.h>

#define N_UTTS 2048
#define SEQ 50
#define DEMB 300
#define DFILT 64
#define DOUT 100
#define NF 192
#define WIND 10
#define HOPS 3
#define NCLS 7
#define NROWS (N_UTTS - 1)
#define KC 150
#define WPITCH 65

// scratch (device globals: allocation-free)
__device__ float g_sutt[N_UTTS * DOUT];
__device__ float g_wihT[100 * 300];
__device__ float g_whhT[100 * 300];
__device__ float g_membank[(size_t)NROWS * WIND * DOUT];
__device__ float g_eps[NROWS * DOUT];

__device__ __forceinline__ float sigmoidf_(float x) { return 1.0f / (1.0f + expf(-x)); }

// ---------------- GRU weight transpose: wT[k*300 + row] = w[row*100 + k] ----------------
__global__ void transpose_gru_kernel(const float* __restrict__ wih, const float* __restrict__ whh) {
    int i = blockIdx.x * blockDim.x + threadIdx.x;
    if (i < 30000) {
        int row = i / 100, k = i - row * 100;
        g_wihT[k * 300 + row] = wih[i];
        g_whhT[k * 300 + row] = whh[i];
    }
}

// ---------------- Fused embedding-gather + conv + relu + maxpool + tanh transform ----------------
// grid = 2048 blocks (one utterance), 128 threads.
// dyn smem: smE[54*300] | smW[KC*WPITCH] | smF[192] | smR[512]
__global__ void __launch_bounds__(128, 2) conv_encoder_kernel(
    const int* __restrict__ sents, const float* __restrict__ emb,
    const float* __restrict__ w3, const float* __restrict__ b3,
    const float* __restrict__ w4, const float* __restrict__ b4,
    const float* __restrict__ w5, const float* __restrict__ b5,
    const float* __restrict__ trans_w, const float* __restrict__ trans_b)
{
    extern __shared__ float sm[];
    float* smE = sm;                       // 54*300 = 16200
    float* smW = smE + 54 * 300;           // KC*WPITCH = 9750
    float* smF = smW + KC * WPITCH;        // 192
    float* smR = smF + NF;                 // 8*64 = 512
    __shared__ int tok[SEQ];

    const int n = blockIdx.x;
    const int tid = threadIdx.x;
    const int ol = tid & 15;      // o-lane 0..15
    const int tg = tid >> 4;      // t-group 0..7

    if (tid < SEQ) tok[tid] = sents[n * SEQ + tid];
    __syncthreads();
    for (int i = tid; i < 54 * 300; i += 128) {
        if (i < SEQ * 300) {
            int t = i / 300, d = i - t * 300;
            smE[i] = emb[(size_t)tok[t] * 300 + d];
        } else {
            smE[i] = 0.0f;
        }
    }
    __syncthreads();

    const float* Ws[3] = { w3, w4, w5 };
    const float* Bs[3] = { b3, b4, b5 };

    for (int g = 0; g < 3; g++) {
        const int fs = 3 + g;
        const float* __restrict__ wg = Ws[g];
        float acc[4][6];
#pragma unroll
        for (int m = 0; m < 4; m++)
#pragma unroll
            for (int i = 0; i < 6; i++) acc[m][i] = 0.0f;

        for (int j = 0; j < fs; j++) {
            for (int k0 = 0; k0 < 300; k0 += KC) {
                __syncthreads();
                // stage W chunk: smW[kk*WPITCH + o] = wg[o*fs*300 + j*300 + k0 + kk]
                for (int li = tid; li < KC * 64; li += 128) {
                    int o = li / KC, kk = li - o * KC;
                    smW[kk * WPITCH + o] = wg[o * fs * 300 + j * 300 + k0 + kk];
                }
                __syncthreads();
                const float* ep = &smE[(tg * 6 + j) * 300 + k0];
#pragma unroll 2
                for (int kk = 0; kk < KC; kk++) {
                    float w0 = smW[kk * WPITCH + ol];
                    float w1 = smW[kk * WPITCH + ol + 16];
                    float w2 = smW[kk * WPITCH + ol + 32];
                    float w3v = smW[kk * WPITCH + ol + 48];
#pragma unroll
                    for (int i = 0; i < 6; i++) {
                        float e = ep[i * 300 + kk];
                        acc[0][i] = fmaf(w0, e, acc[0][i]);
                        acc[1][i] = fmaf(w1, e, acc[1][i]);
                        acc[2][i] = fmaf(w2, e, acc[2][i]);
                        acc[3][i] = fmaf(w3v, e, acc[3][i]);
                    }
                }
            }
        }
        // max over this thread's valid positions
        const int tmax = SEQ - fs;  // t in [0, tmax]
        float mx[4];
#pragma unroll
        for (int m = 0; m < 4; m++) {
            float v = -FLT_MAX;
#pragma unroll
            for (int i = 0; i < 6; i++) {
                int t = tg * 6 + i;
                if (t <= tmax) v = fmaxf(v, acc[m][i]);
            }
            mx[m] = v;
        }
        __syncthreads();
#pragma unroll
        for (int m = 0; m < 4; m++) smR[tg * 64 + ol + 16 * m] = mx[m];
        __syncthreads();
        if (tid < 64) {
            float mm = smR[tid];
#pragma unroll
            for (int q = 1; q < 8; q++) mm = fmaxf(mm, smR[q * 64 + tid]);
            smF[g * 64 + tid] = fmaxf(mm + Bs[g][tid], 0.0f);
        }
    }
    __syncthreads();
    if (tid < DOUT) {
        float s = trans_b[tid];
        const float* tw = &trans_w[tid * NF];
#pragma unroll 4
        for (int c = 0; c < NF; c++) s = fmaf(smF[c], tw[c], s);
        g_sutt[n * DOUT + tid] = tanhf(s);
    }
}

// ---------------- GRU over 10 steps; rows independent across blocks ----------------
#define GRU_ROWS 16
__global__ void gru_kernel(const float* __restrict__ bih, const float* __restrict__ bhh)
{
    __shared__ float sx[GRU_ROWS * DOUT];
    __shared__ float sh[GRU_ROWS * DOUT];
    __shared__ float sgi[GRU_ROWS * 300];
    __shared__ float sgh[GRU_ROWS * 300];

    const int tid = threadIdx.x;  // 320
    const int b0 = blockIdx.x * GRU_ROWS;

    for (int i = tid; i < GRU_ROWS * DOUT; i += 320) sh[i] = 0.0f;

    for (int s = 0; s < WIND; s++) {
        for (int i = tid; i < GRU_ROWS * DOUT; i += 320) {
            int r = i / DOUT, d = i - r * DOUT;
            int b = b0 + r;
            int src = b + s - (WIND - 1);
            sx[i] = (b < NROWS && src >= 0) ? g_sutt[src * DOUT + d] : 0.0f;
        }
        __syncthreads();
        if (tid < 300) {
            float ai[GRU_ROWS], ah[GRU_ROWS];
#pragma unroll
            for (int r = 0; r < GRU_ROWS; r++) { ai[r] = 0.0f; ah[r] = 0.0f; }
            for (int k = 0; k < DOUT; k++) {
                float wi = g_wihT[k * 300 + tid];
                float wh = g_whhT[k * 300 + tid];
#pragma unroll
                for (int r = 0; r < GRU_ROWS; r++) {
                    ai[r] = fmaf(sx[r * DOUT + k], wi, ai[r]);
                    ah[r] = fmaf(sh[r * DOUT + k], wh, ah[r]);
                }
            }
#pragma unroll
            for (int r = 0; r < GRU_ROWS; r++) {
                sgi[r * 300 + tid] = ai[r];
                sgh[r * 300 + tid] = ah[r];
            }
        }
        __syncthreads();
        for (int i = tid; i < GRU_ROWS * DOUT; i += 320) {
            int r = i / DOUT, d = i - r * DOUT;
            int b = b0 + r;
            if (b < NROWS) {
                float ir  = sgi[r * 300 + d]       + bih[d];
                float iz  = sgi[r * 300 + 100 + d] + bih[100 + d];
                float inn = sgi[r * 300 + 200 + d] + bih[200 + d];
                float hr  = sgh[r * 300 + d]       + bhh[d];
                float hz  = sgh[r * 300 + 100 + d] + bhh[100 + d];
                float hn  = sgh[r * 300 + 200 + d] + bhh[200 + d];
                float rr = sigmoidf_(ir + hr);
                float zz = sigmoidf_(iz + hz);
                float nn = tanhf(inn + rr * hn);
                float hnew = (1.0f - zz) * nn + zz * sh[i];
                sh[i] = hnew;
                g_membank[((size_t)b * WIND + s) * DOUT + d] = sx[i] + hnew;
            }
        }
        __syncthreads();
    }
}

// ---------------- Attention: one warp per row b (0..2046) ----------------
__global__ void attn_kernel(float* __restrict__ attn_out)
{
    int gw = (blockIdx.x * blockDim.x + threadIdx.x) >> 5;
    int lane = threadIdx.x & 31;
    if (gw >= NROWS) return;
    const int b = gw;
    const float* __restrict__ mb = g_membank + (size_t)b * WIND * DOUT;

    float e[4];
#pragma unroll
    for (int m = 0; m < 4; m++) {
        int d = lane + 32 * m;
        e[m] = (d < DOUT) ? g_sutt[(b + 1) * DOUT + d] : 0.0f;
    }

    for (int hop = 0; hop < HOPS; hop++) {
        float lg[WIND];
#pragma unroll
        for (int k = 0; k < WIND; k++) {
            float p = 0.0f;
#pragma unroll
            for (int m = 0; m < 4; m++) {
                int d = lane + 32 * m;
                if (d < DOUT) p = fmaf(e[m], mb[k * DOUT + d], p);
            }
#pragma unroll
            for (int off = 16; off > 0; off >>= 1)
                p += __shfl_xor_sync(0xffffffffu, p, off);
            lg[k] = (b + k - (WIND - 1) >= 0) ? p : -1e10f;
        }
        float mx = lg[0];
#pragma unroll
        for (int k = 1; k < WIND; k++) mx = fmaxf(mx, lg[k]);
        float w[WIND], den = 0.0f;
#pragma unroll
        for (int k = 0; k < WIND; k++) { w[k] = expf(lg[k] - mx); den += w[k]; }
        float inv = 1.0f / den;
#pragma unroll
        for (int k = 0; k < WIND; k++) w[k] *= inv;
        if (lane < WIND)
            attn_out[((size_t)hop * NROWS + b) * WIND + lane] = w[lane];
#pragma unroll
        for (int m = 0; m < 4; m++) {
            int d = lane + 32 * m;
            if (d < DOUT) {
                float add = 0.0f;
#pragma unroll
                for (int k = 0; k < WIND; k++)
                    add = fmaf(w[k], mb[k * DOUT + d], add);
                e[m] += add;
            }
        }
    }
#pragma unroll
    for (int m = 0; m < 4; m++) {
        int d = lane + 32 * m;
        if (d < DOUT) g_eps[b * DOUT + d] = e[m];
    }
}

// ---------------- Classifier: one warp per utterance ----------------
__global__ void cls_kernel(const float* __restrict__ cls_w, const float* __restrict__ cls_b,
                           float* __restrict__ pred)
{
    int gw = (blockIdx.x * blockDim.x + threadIdx.x) >> 5;
    int lane = threadIdx.x & 31;
    if (gw >= N_UTTS) return;
    const int n = gw;
    const float* __restrict__ s = (n == 0) ? g_sutt : (g_eps + (size_t)(n - 1) * DOUT);

    float z[NCLS];
#pragma unroll
    for (int c = 0; c < NCLS; c++) z[c] = 0.0f;
    for (int d = lane; d < DOUT; d += 32) {
        float sv = s[d];
#pragma unroll
        for (int c = 0; c < NCLS; c++) z[c] = fmaf(sv, cls_w[c * DOUT + d], z[c]);
    }
#pragma unroll
    for (int c = 0; c < NCLS; c++) {
#pragma unroll
        for (int off = 16; off > 0; off >>= 1)
            z[c] += __shfl_xor_sync(0xffffffffu, z[c], off);
        z[c] += cls_b[c];
    }
    float mx = z[0];
#pragma unroll
    for (int c = 1; c < NCLS; c++) mx = fmaxf(mx, z[c]);
    float den = 0.0f;
#pragma unroll
    for (int c = 0; c < NCLS; c++) den += expf(z[c] - mx);
    float lse = logf(den);
    if (lane < NCLS) pred[(size_t)n * NCLS + lane] = z[lane] - mx - lse;
}

extern "C" void kernel_launch(void* const* d_in, const int* in_sizes, int n_in,
                              void* d_out, int out_size) {
    const int*   sents   = (const int*)  d_in[0];
    // d_in[1] = lengths (unused by reference)
    const float* emb     = (const float*)d_in[2];
    const float* trans_w = (const float*)d_in[3];
    const float* trans_b = (const float*)d_in[4];
    const float* gru_wih = (const float*)d_in[5];
    const float* gru_whh = (const float*)d_in[6];
    const float* gru_bih = (const float*)d_in[7];
    const float* gru_bhh = (const float*)d_in[8];
    const float* cls_w   = (const float*)d_in[9];
    const float* cls_b   = (const float*)d_in[10];
    const float* w3      = (const float*)d_in[11];
    const float* b3      = (const float*)d_in[12];
    const float* w4      = (const float*)d_in[13];
    const float* b4      = (const float*)d_in[14];
    const float* w5      = (const float*)d_in[15];
    const float* b5      = (const float*)d_in[16];

    float* pred = (float*)d_out;                          // 2048*7
    float* attn = (float*)d_out + (size_t)N_UTTS * NCLS;  // 3*2047*10

    // enable >48KB dyn smem for the conv kernel (idempotent host call)
    static int smem_set = 0;
    const int conv_smem = (54 * 300 + KC * WPITCH + NF + 512) * (int)sizeof(float);
    if (!smem_set) {
        cudaFuncSetAttribute(conv_encoder_kernel,
                             cudaFuncAttributeMaxDynamicSharedMemorySize, conv_smem);
        smem_set = 1;
    }

    transpose_gru_kernel<<<(30000 + 255) / 256, 256>>>(gru_wih, gru_whh);
    conv_encoder_kernel<<<N_UTTS, 128, conv_smem>>>(
        sents, emb, w3, b3, w4, b4, w5, b5, trans_w, trans_b);
    gru_kernel<<<(NROWS + GRU_ROWS - 1) / GRU_ROWS, 320>>>(gru_bih, gru_bhh);
    attn_kernel<<<(NROWS * 32 + 127) / 128, 128>>>(attn);
    cls_kernel<<<(N_UTTS * 32 + 127) / 128, 128>>>(cls_w, cls_b, pred);
}

// round 8
// speedup vs baseline: 2.3276x; 2.3276x over previous
#include <cuda_runtime.h>
#include <cuda_bf16.h>
#include <math.h>
#include <float.h>
#include <stdint.h>

#define N_UTTS 2048
#define SEQ 50
#define DOUT 100
#define NF 192
#define WIND 10
#define HOPS 3
#define NCLS 7
#define NROWS (N_UTTS - 1)
#define NPAIRS 1024
#define E_ROWS 136
#define E_PITCH 304
#define NCHUNKS 25

#define OFF_A(buf, hl) (((buf) * 2 + (hl)) * 16384)
#define OFF_B(buf, hl) (65536 + ((buf) * 2 + (hl)) * 24576)
#define CONV_SMEM 163840

__device__ __align__(128) __nv_bfloat16 g_Eh[(size_t)NPAIRS * E_ROWS * E_PITCH];
__device__ __align__(128) __nv_bfloat16 g_El[(size_t)NPAIRS * E_ROWS * E_PITCH];
__device__ __align__(128) __nv_bfloat16 g_Bh[NCHUNKS * 12288];
__device__ __align__(128) __nv_bfloat16 g_Bl[NCHUNKS * 12288];
__device__ float g_sutt[N_UTTS * DOUT];
__device__ float g_wihT[100 * 300];
__device__ float g_whhT[100 * 300];
__device__ float g_membank[(size_t)NROWS * WIND * DOUT];
__device__ float g_eps[NROWS * DOUT];

__device__ __forceinline__ float sigmoidf_(float x) { return 1.0f / (1.0f + expf(-x)); }

__device__ __forceinline__ uint32_t smem_to_u32(const void* p) {
    uint32_t a;
    asm("{ .reg .u64 t; cvta.to.shared.u64 t, %1; cvt.u32.u64 %0, t; }" : "=r"(a) : "l"(p));
    return a;
}
__device__ __forceinline__ void cp16(uint32_t dst, const void* src) {
    asm volatile("cp.async.cg.shared.global [%0], [%1], 16;" :: "r"(dst), "l"(src) : "memory");
}
__device__ __forceinline__ uint32_t swz(uint32_t b) { return b ^ ((b >> 3) & 0x70); }

__device__ __forceinline__ void ldsm4(uint32_t r[4], uint32_t addr) {
    asm volatile("ldmatrix.sync.aligned.m8n8.x4.shared.b16 {%0,%1,%2,%3}, [%4];"
                 : "=r"(r[0]), "=r"(r[1]), "=r"(r[2]), "=r"(r[3]) : "r"(addr));
}
__device__ __forceinline__ void mma16816(float c[4], const uint32_t a[4], uint32_t b0, uint32_t b1) {
    asm volatile("mma.sync.aligned.m16n8k16.row.col.f32.bf16.bf16.f32 "
                 "{%0,%1,%2,%3}, {%4,%5,%6,%7}, {%8,%9}, {%0,%1,%2,%3};"
                 : "+f"(c[0]), "+f"(c[1]), "+f"(c[2]), "+f"(c[3])
                 : "r"(a[0]), "r"(a[1]), "r"(a[2]), "r"(a[3]), "r"(b0), "r"(b1));
}

// ---- prep: hi/lo bf16 embeddings, plain layout ----
__global__ void prep_e_kernel(const int* __restrict__ sents, const float* __restrict__ emb) {
    int rg = blockIdx.x, k = threadIdx.x;
    int p = rg / E_ROWS, r = rg % E_ROWS;
    float x = 0.0f;
    if (r < 108 && k < 300) {
        int u = (r >= 54), t = r - 54 * u;
        if (t < SEQ) x = emb[(size_t)sents[(2 * p + u) * SEQ + t] * 300 + k];
    }
    __nv_bfloat16 h = __float2bfloat16(x);
    __nv_bfloat16 l = __float2bfloat16(x - __bfloat162float(h));
    size_t o = (size_t)rg * E_PITCH + k;
    g_Eh[o] = h; g_El[o] = l;
}

// ---- prep: pre-swizzled hi/lo weight tiles, zero-padded over j>=fs, k>=300 ----
__global__ void prep_b_kernel(const float* __restrict__ w3, const float* __restrict__ w4,
                              const float* __restrict__ w5) {
    int idx = blockIdx.x * 256 + threadIdx.x;
    if (idx >= NCHUNKS * 12288) return;
    int k = idx & 63, n = (idx >> 6) % 192, ch = idx / 12288;
    int j = ch / 5, cc = ch % 5, kg = cc * 64 + k;
    int g = n >> 6, o = n & 63, fs = 3 + g;
    float x = 0.0f;
    if (j < fs && kg < 300) {
        const float* w = (g == 0) ? w3 : (g == 1) ? w4 : w5;
        x = w[(o * fs + j) * 300 + kg];
    }
    __nv_bfloat16 h = __float2bfloat16(x);
    __nv_bfloat16 l = __float2bfloat16(x - __bfloat162float(h));
    uint32_t sw = swz((uint32_t)n * 128 + (uint32_t)k * 2);
    size_t d = (size_t)ch * 12288 + (sw >> 1);
    g_Bh[d] = h; g_Bl[d] = l;
}

__global__ void transpose_gru_kernel(const float* __restrict__ wih, const float* __restrict__ whh) {
    int i = blockIdx.x * blockDim.x + threadIdx.x;
    if (i < 30000) {
        int row = i / 100, k = i - row * 100;
        g_wihT[k * 300 + row] = wih[i];
        g_whhT[k * 300 + row] = whh[i];
    }
}

// ---- conv mainloop staging: A swizzled at STS-time, B straight 16B copy ----
__device__ __forceinline__ void stage_chunk(int p, int ch, int buf, uint32_t smb, int tid) {
    int j = ch / 5, c = ch % 5;
    uint32_t ah = smb + OFF_A(buf, 0), al = smb + OFF_A(buf, 1);
    size_t base = (size_t)p * (E_ROWS * E_PITCH) + (size_t)j * E_PITCH + c * 64;
#pragma unroll
    for (int it = 0; it < 4; it++) {
        int idx = tid + it * 256;       // 0..1023 -> (row 0..127, u 0..7)
        int row = idx >> 3, u = idx & 7;
        size_t src = base + (size_t)row * E_PITCH + u * 8;
        uint32_t d = swz((uint32_t)row * 128 + (uint32_t)u * 16);
        cp16(ah + d, g_Eh + src);
        cp16(al + d, g_El + src);
    }
    uint32_t bh = smb + OFF_B(buf, 0), bl = smb + OFF_B(buf, 1);
    const char* gh = (const char*)(g_Bh + (size_t)ch * 12288);
    const char* gl = (const char*)(g_Bl + (size_t)ch * 12288);
#pragma unroll
    for (int it = 0; it < 6; it++) {
        int idx = tid + it * 256;       // 0..1535
        cp16(bh + idx * 16, gh + idx * 16);
        cp16(bl + idx * 16, gl + idx * 16);
    }
}

// ---- conv GEMM via warp HMMA (mma.sync bf16, 3-pass hi/lo split) ----
__global__ void __launch_bounds__(256, 1) conv_mma_kernel(
    const float* __restrict__ b3, const float* __restrict__ b4, const float* __restrict__ b5,
    const float* __restrict__ trans_w, const float* __restrict__ trans_b)
{
    extern __shared__ char smem[];
    const uint32_t smb = smem_to_u32(smem);
    const int tid = threadIdx.x, wid = tid >> 5, lane = tid & 31;
    const int p = blockIdx.x;
    const int wm = wid & 3, wn = wid >> 2;     // 4 M-blocks x 2 N-blocks

    float acc[2][12][4];
#pragma unroll
    for (int m = 0; m < 2; m++)
#pragma unroll
        for (int nf = 0; nf < 12; nf++)
#pragma unroll
            for (int q = 0; q < 4; q++) acc[m][nf][q] = 0.0f;

    stage_chunk(p, 0, 0, smb, tid);
    asm volatile("cp.async.commit_group;" ::: "memory");

    // precomputed lane address components
    const int arow = wm * 32 + (lane & 15);            // A: lanes 0-15 rows, 16-31 same rows +16B
    const int acol16 = (lane >> 4) * 16;
    const int bnrow = wn * 96 + (lane & 7) + ((lane >> 4) << 3);  // B: n row
    const int bcol16 = ((lane >> 3) & 1) << 4;

    for (int ch = 0; ch < NCHUNKS; ch++) {
        int buf = ch & 1;
        if (ch + 1 < NCHUNKS) {
            stage_chunk(p, ch + 1, 1 - buf, smb, tid);
            asm volatile("cp.async.commit_group;" ::: "memory");
            asm volatile("cp.async.wait_group 1;" ::: "memory");
        } else {
            asm volatile("cp.async.wait_group 0;" ::: "memory");
        }
        __syncthreads();

        const uint32_t aH = smb + OFF_A(buf, 0), aL = smb + OFF_A(buf, 1);
        const uint32_t bH = smb + OFF_B(buf, 0), bL = smb + OFF_B(buf, 1);
#pragma unroll
        for (int ks = 0; ks < 4; ks++) {
            uint32_t ah[2][4], al[2][4];
            const int abc = ks * 32 + acol16;
#pragma unroll
            for (int f = 0; f < 2; f++) {
                uint32_t off = swz((uint32_t)(arow + f * 16) * 128 + abc);
                ldsm4(ah[f], aH + off);
                ldsm4(al[f], aL + off);
            }
            const int bbc = ks * 32 + bcol16;
#pragma unroll
            for (int i = 0; i < 6; i++) {
                uint32_t off = swz((uint32_t)(bnrow + i * 16) * 128 + bbc);
                uint32_t bh4[4], bl4[4];
                ldsm4(bh4, bH + off);
                ldsm4(bl4, bL + off);
#pragma unroll
                for (int m = 0; m < 2; m++) {
                    mma16816(acc[m][2 * i],     ah[m], bh4[0], bh4[1]);
                    mma16816(acc[m][2 * i],     ah[m], bl4[0], bl4[1]);
                    mma16816(acc[m][2 * i],     al[m], bh4[0], bh4[1]);
                    mma16816(acc[m][2 * i + 1], ah[m], bh4[2], bh4[3]);
                    mma16816(acc[m][2 * i + 1], ah[m], bl4[2], bl4[3]);
                    mma16816(acc[m][2 * i + 1], al[m], bh4[2], bh4[3]);
                }
            }
        }
        __syncthreads();   // all warps done reading buf before it is restaged
    }

    // ---- epilogue: acc regs -> smD (pitch 193) -> maxpool -> transform ----
    float* smD = (float*)smem;     // 128*193 floats = 98816 B, overlays staging buffers
    const int g = lane >> 2, t = lane & 3;
#pragma unroll
    for (int m = 0; m < 2; m++)
#pragma unroll
        for (int nf = 0; nf < 12; nf++) {
            int row = wm * 32 + m * 16 + g;
            int col = wn * 96 + nf * 8 + t * 2;
            smD[row * 193 + col]           = acc[m][nf][0];
            smD[row * 193 + col + 1]       = acc[m][nf][1];
            smD[(row + 8) * 193 + col]     = acc[m][nf][2];
            smD[(row + 8) * 193 + col + 1] = acc[m][nf][3];
        }
    __syncthreads();

    float* smF = (float*)(smem + 131072);
    for (int i = tid; i < 2 * NF; i += 256) {
        int u = i / NF, o = i - u * NF, gg = o >> 6;
        int tmaxv = 47 - gg;
        float v = -FLT_MAX;
        for (int tt = 0; tt <= tmaxv; tt++) v = fmaxf(v, smD[(u * 54 + tt) * 193 + o]);
        float bias = (gg == 0) ? b3[o] : (gg == 1) ? b4[o - 64] : b5[o - 128];
        smF[i] = fmaxf(v + bias, 0.0f);
    }
    __syncthreads();
    if (tid < 200) {
        int u = tid / 100, d = tid - u * 100;
        float s = trans_b[d];
        const float* tw = trans_w + d * NF;
        const float* f = smF + u * NF;
#pragma unroll 4
        for (int c2 = 0; c2 < NF; c2++) s = fmaf(f[c2], tw[c2], s);
        g_sutt[(2 * p + u) * DOUT + d] = tanhf(s);
    }
}

// ---------------- GRU ----------------
#define GRU_ROWS 16
__global__ void gru_kernel(const float* __restrict__ bih, const float* __restrict__ bhh)
{
    __shared__ float sx[GRU_ROWS * DOUT];
    __shared__ float sh[GRU_ROWS * DOUT];
    __shared__ float sgi[GRU_ROWS * 300];
    __shared__ float sgh[GRU_ROWS * 300];
    const int tid = threadIdx.x;
    const int b0 = blockIdx.x * GRU_ROWS;
    for (int i = tid; i < GRU_ROWS * DOUT; i += 320) sh[i] = 0.0f;
    for (int s = 0; s < WIND; s++) {
        for (int i = tid; i < GRU_ROWS * DOUT; i += 320) {
            int r = i / DOUT, d = i - r * DOUT;
            int b = b0 + r, src = b + s - (WIND - 1);
            sx[i] = (b < NROWS && src >= 0) ? g_sutt[src * DOUT + d] : 0.0f;
        }
        __syncthreads();
        if (tid < 300) {
            float ai[GRU_ROWS], ah[GRU_ROWS];
#pragma unroll
            for (int r = 0; r < GRU_ROWS; r++) { ai[r] = 0.0f; ah[r] = 0.0f; }
            for (int k = 0; k < DOUT; k++) {
                float wi = g_wihT[k * 300 + tid];
                float wh = g_whhT[k * 300 + tid];
#pragma unroll
                for (int r = 0; r < GRU_ROWS; r++) {
                    ai[r] = fmaf(sx[r * DOUT + k], wi, ai[r]);
                    ah[r] = fmaf(sh[r * DOUT + k], wh, ah[r]);
                }
            }
#pragma unroll
            for (int r = 0; r < GRU_ROWS; r++) { sgi[r * 300 + tid] = ai[r]; sgh[r * 300 + tid] = ah[r]; }
        }
        __syncthreads();
        for (int i = tid; i < GRU_ROWS * DOUT; i += 320) {
            int r = i / DOUT, d = i - r * DOUT;
            int b = b0 + r;
            if (b < NROWS) {
                float ir = sgi[r * 300 + d] + bih[d];
                float iz = sgi[r * 300 + 100 + d] + bih[100 + d];
                float inn = sgi[r * 300 + 200 + d] + bih[200 + d];
                float hr = sgh[r * 300 + d] + bhh[d];
                float hz = sgh[r * 300 + 100 + d] + bhh[100 + d];
                float hn = sgh[r * 300 + 200 + d] + bhh[200 + d];
                float rr = sigmoidf_(ir + hr);
                float zz = sigmoidf_(iz + hz);
                float nn = tanhf(inn + rr * hn);
                float hnew = (1.0f - zz) * nn + zz * sh[i];
                sh[i] = hnew;
                g_membank[((size_t)b * WIND + s) * DOUT + d] = sx[i] + hnew;
            }
        }
        __syncthreads();
    }
}

// ---------------- Attention ----------------
__global__ void attn_kernel(float* __restrict__ attn_out)
{
    int gw = (blockIdx.x * blockDim.x + threadIdx.x) >> 5;
    int lane = threadIdx.x & 31;
    if (gw >= NROWS) return;
    const int b = gw;
    const float* __restrict__ mb = g_membank + (size_t)b * WIND * DOUT;
    float e[4];
#pragma unroll
    for (int m = 0; m < 4; m++) {
        int d = lane + 32 * m;
        e[m] = (d < DOUT) ? g_sutt[(b + 1) * DOUT + d] : 0.0f;
    }
    for (int hop = 0; hop < HOPS; hop++) {
        float lg[WIND];
#pragma unroll
        for (int k = 0; k < WIND; k++) {
            float p = 0.0f;
#pragma unroll
            for (int m = 0; m < 4; m++) {
                int d = lane + 32 * m;
                if (d < DOUT) p = fmaf(e[m], mb[k * DOUT + d], p);
            }
#pragma unroll
            for (int off = 16; off > 0; off >>= 1) p += __shfl_xor_sync(0xffffffffu, p, off);
            lg[k] = (b + k - (WIND - 1) >= 0) ? p : -1e10f;
        }
        float mx = lg[0];
#pragma unroll
        for (int k = 1; k < WIND; k++) mx = fmaxf(mx, lg[k]);
        float w[WIND], den = 0.0f;
#pragma unroll
        for (int k = 0; k < WIND; k++) { w[k] = expf(lg[k] - mx); den += w[k]; }
        float inv = 1.0f / den;
#pragma unroll
        for (int k = 0; k < WIND; k++) w[k] *= inv;
        if (lane < WIND) attn_out[((size_t)hop * NROWS + b) * WIND + lane] = w[lane];
#pragma unroll
        for (int m = 0; m < 4; m++) {
            int d = lane + 32 * m;
            if (d < DOUT) {
                float add = 0.0f;
#pragma unroll
                for (int k = 0; k < WIND; k++) add = fmaf(w[k], mb[k * DOUT + d], add);
                e[m] += add;
            }
        }
    }
#pragma unroll
    for (int m = 0; m < 4; m++) {
        int d = lane + 32 * m;
        if (d < DOUT) g_eps[b * DOUT + d] = e[m];
    }
}

// ---------------- Classifier ----------------
__global__ void cls_kernel(const float* __restrict__ cls_w, const float* __restrict__ cls_b,
                           float* __restrict__ pred)
{
    int gw = (blockIdx.x * blockDim.x + threadIdx.x) >> 5;
    int lane = threadIdx.x & 31;
    if (gw >= N_UTTS) return;
    const int n = gw;
    const float* __restrict__ s = (n == 0) ? g_sutt : (g_eps + (size_t)(n - 1) * DOUT);
    float z[NCLS];
#pragma unroll
    for (int c = 0; c < NCLS; c++) z[c] = 0.0f;
    for (int d = lane; d < DOUT; d += 32) {
        float sv = s[d];
#pragma unroll
        for (int c = 0; c < NCLS; c++) z[c] = fmaf(sv, cls_w[c * DOUT + d], z[c]);
    }
#pragma unroll
    for (int c = 0; c < NCLS; c++) {
#pragma unroll
        for (int off = 16; off > 0; off >>= 1) z[c] += __shfl_xor_sync(0xffffffffu, z[c], off);
        z[c] += cls_b[c];
    }
    float mx = z[0];
#pragma unroll
    for (int c = 1; c < NCLS; c++) mx = fmaxf(mx, z[c]);
    float den = 0.0f;
#pragma unroll
    for (int c = 0; c < NCLS; c++) den += expf(z[c] - mx);
    float lse = logf(den);
    if (lane < NCLS) pred[(size_t)n * NCLS + lane] = z[lane] - mx - lse;
}

extern "C" void kernel_launch(void* const* d_in, const int* in_sizes, int n_in,
                              void* d_out, int out_size) {
    const int*   sents   = (const int*)  d_in[0];
    const float* emb     = (const float*)d_in[2];
    const float* trans_w = (const float*)d_in[3];
    const float* trans_b = (const float*)d_in[4];
    const float* gru_wih = (const float*)d_in[5];
    const float* gru_whh = (const float*)d_in[6];
    const float* gru_bih = (const float*)d_in[7];
    const float* gru_bhh = (const float*)d_in[8];
    const float* cls_w   = (const float*)d_in[9];
    const float* cls_b   = (const float*)d_in[10];
    const float* w3      = (const float*)d_in[11];
    const float* b3      = (const float*)d_in[12];
    const float* w4      = (const float*)d_in[13];
    const float* b4      = (const float*)d_in[14];
    const float* w5      = (const float*)d_in[15];
    const float* b5      = (const float*)d_in[16];

    float* pred = (float*)d_out;
    float* attn = (float*)d_out + (size_t)N_UTTS * NCLS;

    static int once = 0;
    if (!once) {
        cudaFuncSetAttribute(conv_mma_kernel, cudaFuncAttributeMaxDynamicSharedMemorySize, CONV_SMEM);
        once = 1;
    }

    transpose_gru_kernel<<<(30000 + 255) / 256, 256>>>(gru_wih, gru_whh);
    prep_e_kernel<<<NPAIRS * E_ROWS, E_PITCH>>>(sents, emb);
    prep_b_kernel<<<(NCHUNKS * 12288 + 255) / 256, 256>>>(w3, w4, w5);
    conv_mma_kernel<<<NPAIRS, 256, CONV_SMEM>>>(b3, b4, b5, trans_w, trans_b);
    gru_kernel<<<(NROWS + GRU_ROWS - 1) / GRU_ROWS, 320>>>(gru_bih, gru_bhh);
    attn_kernel<<<(NROWS * 32 + 127) / 128, 128>>>(attn);
    cls_kernel<<<(N_UTTS * 32 + 127) / 128, 128>>>(cls_w, cls_b, pred);
}

// round 12
// speedup vs baseline: 2.6346x; 1.1319x over previous
#include <cuda_runtime.h>
#include <cuda_bf16.h>
#include <math.h>
#include <float.h>
#include <stdint.h>

#define N_UTTS 2048
#define SEQ 50
#define DOUT 100
#define NF 192
#define WIND 10
#define HOPS 3
#define NCLS 7
#define NROWS (N_UTTS - 1)
#define NPAIRS 1024
#define E_ROWS 136
#define E_PITCH 304
#define NCHUNKS 50          // 5 j-shifts x 10 k-chunks of 32

// smem layout (bytes): A buffers 4x8KB, B buffers 4x12KB = 80KB staging;
// epilogue overlays: smD 128*193*4 = 98816, smF at 98816 (1536B)
#define OFF_A(buf, hl) (((buf) * 2 + (hl)) * 8192)
#define OFF_B(buf, hl) (32768 + ((buf) * 2 + (hl)) * 12288)
#define CONV_SMEM 100480

__device__ __align__(128) __nv_bfloat16 g_Eh[(size_t)NPAIRS * E_ROWS * E_PITCH];
__device__ __align__(128) __nv_bfloat16 g_El[(size_t)NPAIRS * E_ROWS * E_PITCH];
__device__ __align__(128) __nv_bfloat16 g_Bh[NCHUNKS * 6144];
__device__ __align__(128) __nv_bfloat16 g_Bl[NCHUNKS * 6144];
__device__ float g_sutt[N_UTTS * DOUT];
__device__ float g_wihT[100 * 300];
__device__ float g_whhT[100 * 300];
__device__ float g_membank[(size_t)NROWS * WIND * DOUT];
__device__ float g_eps[NROWS * DOUT];

__device__ __forceinline__ float sigmoidf_(float x) { return 1.0f / (1.0f + expf(-x)); }

__device__ __forceinline__ uint32_t smem_to_u32(const void* p) {
    uint32_t a;
    asm("{ .reg .u64 t; cvta.to.shared.u64 t, %1; cvt.u32.u64 %0, t; }" : "=r"(a) : "l"(p));
    return a;
}
__device__ __forceinline__ void cp16(uint32_t dst, const void* src) {
    asm volatile("cp.async.cg.shared.global [%0], [%1], 16;" :: "r"(dst), "l"(src) : "memory");
}
// SW64 swizzle: 64B row pitch, XOR bits[5:4] with bits[8:7]
__device__ __host__ __forceinline__ uint32_t swz64(uint32_t b) { return b ^ ((b >> 3) & 0x30); }

__device__ __forceinline__ void ldsm4(uint32_t r[4], uint32_t addr) {
    asm volatile("ldmatrix.sync.aligned.m8n8.x4.shared.b16 {%0,%1,%2,%3}, [%4];"
                 : "=r"(r[0]), "=r"(r[1]), "=r"(r[2]), "=r"(r[3]) : "r"(addr));
}
__device__ __forceinline__ void mma16816(float c[4], const uint32_t a[4], uint32_t b0, uint32_t b1) {
    asm volatile("mma.sync.aligned.m16n8k16.row.col.f32.bf16.bf16.f32 "
                 "{%0,%1,%2,%3}, {%4,%5,%6,%7}, {%8,%9}, {%0,%1,%2,%3};"
                 : "+f"(c[0]), "+f"(c[1]), "+f"(c[2]), "+f"(c[3])
                 : "r"(a[0]), "r"(a[1]), "r"(a[2]), "r"(a[3]), "r"(b0), "r"(b1));
}

// ---- prep: hi/lo bf16 embeddings, vectorized (float2 in, bf16x2 out) ----
__global__ void __launch_bounds__(256) prep_e_kernel(const int* __restrict__ sents,
                                                     const float* __restrict__ emb) {
    __shared__ int tok[100];
    const int p = blockIdx.x, tid = threadIdx.x;
    if (tid < 100) tok[tid] = sents[(2 * p + tid / 50) * SEQ + tid % 50];
    __syncthreads();
    uint32_t* outH = (uint32_t*)g_Eh + (size_t)p * (E_ROWS * E_PITCH / 2);
    uint32_t* outL = (uint32_t*)g_El + (size_t)p * (E_ROWS * E_PITCH / 2);
    for (int i = tid; i < E_ROWS * (E_PITCH / 2); i += 256) {
        int r = i / (E_PITCH / 2), c2 = i - r * (E_PITCH / 2);
        float x0 = 0.0f, x1 = 0.0f;
        if (r < 108 && c2 < 150) {
            int u = (r >= 54), t = r - 54 * u;
            if (t < SEQ) {
                float2 v = *(const float2*)(emb + (size_t)tok[u * 50 + t] * 300 + 2 * c2);
                x0 = v.x; x1 = v.y;
            }
        }
        __nv_bfloat16 h0 = __float2bfloat16(x0), h1 = __float2bfloat16(x1);
        __nv_bfloat16 l0 = __float2bfloat16(x0 - __bfloat162float(h0));
        __nv_bfloat16 l1 = __float2bfloat16(x1 - __bfloat162float(h1));
        outH[i] = ((uint32_t)__bfloat16_as_ushort(h1) << 16) | __bfloat16_as_ushort(h0);
        outL[i] = ((uint32_t)__bfloat16_as_ushort(l1) << 16) | __bfloat16_as_ushort(l0);
    }
}

// ---- prep: pre-swizzled (SW64) hi/lo weight tiles with PERMUTED columns ----
// n' layout per tile: [h=0: g0 o0-31 | g1 o0-31 | g2 o0-31 | h=1: g0 o32-63 | g1 | g2]
__global__ void prep_b_kernel(const float* __restrict__ w3, const float* __restrict__ w4,
                              const float* __restrict__ w5) {
    int idx = blockIdx.x * 256 + threadIdx.x;
    if (idx >= NCHUNKS * 6144) return;
    int k = idx & 31, n = (idx >> 5) % 192, ch = idx / 6144;
    int j = ch / 10, c = ch % 10, kg = c * 32 + k;
    int h = n / 96, r96 = n % 96, g = r96 >> 5, o = h * 32 + (r96 & 31);
    int fs = 3 + g;
    float x = 0.0f;
    if (j < fs && kg < 300) {
        const float* w = (g == 0) ? w3 : (g == 1) ? w4 : w5;
        x = w[(o * fs + j) * 300 + kg];
    }
    __nv_bfloat16 hh = __float2bfloat16(x);
    __nv_bfloat16 ll = __float2bfloat16(x - __bfloat162float(hh));
    uint32_t sw = swz64((uint32_t)n * 64 + (uint32_t)k * 2);
    size_t d = (size_t)ch * 6144 + (sw >> 1);
    g_Bh[d] = hh; g_Bl[d] = ll;
}

__global__ void transpose_gru_kernel(const float* __restrict__ wih, const float* __restrict__ whh) {
    int i = blockIdx.x * blockDim.x + threadIdx.x;
    if (i < 30000) {
        int row = i / 100, k = i - row * 100;
        g_wihT[k * 300 + row] = wih[i];
        g_whhT[k * 300 + row] = whh[i];
    }
}

// ---- conv staging: A swizzled at cp-time, B straight 16B copy (pre-swizzled) ----
__device__ __forceinline__ void stage_chunk(int p, int ch, int buf, uint32_t smb, int tid) {
    int j = ch / 10, c = ch % 10;
    uint32_t ah = smb + OFF_A(buf, 0), al = smb + OFF_A(buf, 1);
    size_t base = (size_t)p * (E_ROWS * E_PITCH) + (size_t)j * E_PITCH + c * 32;
#pragma unroll
    for (int it = 0; it < 2; it++) {
        int idx = tid + it * 256;       // 0..511 -> (row 0..127, u 0..3)
        int row = idx >> 2, u = idx & 3;
        size_t src = base + (size_t)row * E_PITCH + u * 8;
        uint32_t d = swz64((uint32_t)row * 64 + (uint32_t)u * 16);
        cp16(ah + d, g_Eh + src);
        cp16(al + d, g_El + src);
    }
    uint32_t bh = smb + OFF_B(buf, 0), bl = smb + OFF_B(buf, 1);
    const char* gh = (const char*)(g_Bh + (size_t)ch * 6144);
    const char* gl = (const char*)(g_Bl + (size_t)ch * 6144);
#pragma unroll
    for (int it = 0; it < 3; it++) {
        int idx = tid + it * 256;       // 0..767 -> (row 0..191, u 0..3)
        int row = idx >> 2;
        int g = (row % 96) >> 5;
        if (j < 3 + g) {                // skip staging of zero-weight groups
            cp16(bh + idx * 16, gh + idx * 16);
            cp16(bl + idx * 16, gl + idx * 16);
        }
    }
}

// ---- conv GEMM via warp HMMA (mma.sync bf16, 3-pass hi/lo split) ----
__global__ void __launch_bounds__(256, 1) conv_mma_kernel(
    const float* __restrict__ b3, const float* __restrict__ b4, const float* __restrict__ b5,
    const float* __restrict__ trans_w, const float* __restrict__ trans_b)
{
    extern __shared__ char smem[];
    const uint32_t smb = smem_to_u32(smem);
    const int tid = threadIdx.x, wid = tid >> 5, lane = tid & 31;
    const int p = blockIdx.x;
    const int wm = wid & 3, wn = wid >> 2;     // 4 M-blocks x 2 N-blocks (96 permuted cols)

    float acc[2][12][4];
#pragma unroll
    for (int m = 0; m < 2; m++)
#pragma unroll
        for (int nf = 0; nf < 12; nf++)
#pragma unroll
            for (int q = 0; q < 4; q++) acc[m][nf][q] = 0.0f;

    stage_chunk(p, 0, 0, smb, tid);
    asm volatile("cp.async.commit_group;" ::: "memory");

    const int arow = wm * 32 + (lane & 15);
    const int acol16 = (lane >> 4) * 16;
    const int bnrow = wn * 96 + (lane & 7) + ((lane >> 4) << 3);
    const int bcol16 = ((lane >> 3) & 1) << 4;

    for (int ch = 0; ch < NCHUNKS; ch++) {
        int buf = ch & 1;
        if (ch + 1 < NCHUNKS) {
            stage_chunk(p, ch + 1, 1 - buf, smb, tid);
            asm volatile("cp.async.commit_group;" ::: "memory");
            asm volatile("cp.async.wait_group 1;" ::: "memory");
        } else {
            asm volatile("cp.async.wait_group 0;" ::: "memory");
        }
        __syncthreads();

        const int j = ch / 10;
        const uint32_t aH = smb + OFF_A(buf, 0), aL = smb + OFF_A(buf, 1);
        const uint32_t bH = smb + OFF_B(buf, 0), bL = smb + OFF_B(buf, 1);
#pragma unroll
        for (int ks = 0; ks < 2; ks++) {
            uint32_t ah[2][4], al[2][4];
            const int abc = ks * 32 + acol16;
#pragma unroll
            for (int f = 0; f < 2; f++) {
                uint32_t off = swz64((uint32_t)(arow + f * 16) * 64 + abc);
                ldsm4(ah[f], aH + off);
                ldsm4(al[f], aL + off);
            }
            const int bbc = ks * 32 + bcol16;
#pragma unroll
            for (int i = 0; i < 6; i++) {
                // i0,1 -> g0 (valid j<3); i2,3 -> g1 (j<4); i4,5 -> g2 (always)
                if (i < 2 && j >= 3) continue;
                if (i < 4 && j >= 4) continue;
                uint32_t off = swz64((uint32_t)(bnrow + i * 16) * 64 + bbc);
                uint32_t bh4[4], bl4[4];
                ldsm4(bh4, bH + off);
                ldsm4(bl4, bL + off);
#pragma unroll
                for (int m = 0; m < 2; m++) {
                    mma16816(acc[m][2 * i],     ah[m], bh4[0], bh4[1]);
                    mma16816(acc[m][2 * i],     ah[m], bl4[0], bl4[1]);
                    mma16816(acc[m][2 * i],     al[m], bh4[0], bh4[1]);
                    mma16816(acc[m][2 * i + 1], ah[m], bh4[2], bh4[3]);
                    mma16816(acc[m][2 * i + 1], ah[m], bl4[2], bl4[3]);
                    mma16816(acc[m][2 * i + 1], al[m], bh4[2], bh4[3]);
                }
            }
        }
        __syncthreads();
    }

    // ---- epilogue: acc -> smD (permuted cols, pitch 193) -> maxpool -> transform ----
    float* smD = (float*)smem;
    const int g = lane >> 2, t = lane & 3;
#pragma unroll
    for (int m = 0; m < 2; m++)
#pragma unroll
        for (int nf = 0; nf < 12; nf++) {
            int row = wm * 32 + m * 16 + g;
            int col = wn * 96 + nf * 8 + t * 2;
            smD[row * 193 + col]           = acc[m][nf][0];
            smD[row * 193 + col + 1]       = acc[m][nf][1];
            smD[(row + 8) * 193 + col]     = acc[m][nf][2];
            smD[(row + 8) * 193 + col + 1] = acc[m][nf][3];
        }
    __syncthreads();

    float* smF = (float*)(smem + 98816);
    for (int i = tid; i < 2 * NF; i += 256) {
        int u = i / NF, o = i - u * NF;
        int gg = o >> 6, oo = o & 63;
        int colp = (oo >> 5) * 96 + gg * 32 + (oo & 31);   // permuted column
        int tmaxv = 47 - gg;
        float v = -FLT_MAX;
        for (int tt = 0; tt <= tmaxv; tt++) v = fmaxf(v, smD[(u * 54 + tt) * 193 + colp]);
        float bias = (gg == 0) ? b3[o] : (gg == 1) ? b4[o - 64] : b5[o - 128];
        smF[i] = fmaxf(v + bias, 0.0f);
    }
    __syncthreads();
    if (tid < 200) {
        int u = tid / 100, d = tid - u * 100;
        float s = trans_b[d];
        const float* tw = trans_w + d * NF;
        const float* f = smF + u * NF;
#pragma unroll 4
        for (int c2 = 0; c2 < NF; c2++) s = fmaf(f[c2], tw[c2], s);
        g_sutt[(2 * p + u) * DOUT + d] = tanhf(s);
    }
}

// ---------------- GRU ----------------
#define GRU_ROWS 16
__global__ void gru_kernel(const float* __restrict__ bih, const float* __restrict__ bhh)
{
    __shared__ float sx[GRU_ROWS * DOUT];
    __shared__ float sh[GRU_ROWS * DOUT];
    __shared__ float sgi[GRU_ROWS * 300];
    __shared__ float sgh[GRU_ROWS * 300];
    const int tid = threadIdx.x;
    const int b0 = blockIdx.x * GRU_ROWS;
    for (int i = tid; i < GRU_ROWS * DOUT; i += 320) sh[i] = 0.0f;
    for (int s = 0; s < WIND; s++) {
        for (int i = tid; i < GRU_ROWS * DOUT; i += 320) {
            int r = i / DOUT, d = i - r * DOUT;
            int b = b0 + r, src = b + s - (WIND - 1);
            sx[i] = (b < NROWS && src >= 0) ? g_sutt[src * DOUT + d] : 0.0f;
        }
        __syncthreads();
        if (tid < 300) {
            float ai[GRU_ROWS], ah[GRU_ROWS];
#pragma unroll
            for (int r = 0; r < GRU_ROWS; r++) { ai[r] = 0.0f; ah[r] = 0.0f; }
            for (int k = 0; k < DOUT; k++) {
                float wi = g_wihT[k * 300 + tid];
                float wh = g_whhT[k * 300 + tid];
#pragma unroll
                for (int r = 0; r < GRU_ROWS; r++) {
                    ai[r] = fmaf(sx[r * DOUT + k], wi, ai[r]);
                    ah[r] = fmaf(sh[r * DOUT + k], wh, ah[r]);
                }
            }
#pragma unroll
            for (int r = 0; r < GRU_ROWS; r++) { sgi[r * 300 + tid] = ai[r]; sgh[r * 300 + tid] = ah[r]; }
        }
        __syncthreads();
        for (int i = tid; i < GRU_ROWS * DOUT; i += 320) {
            int r = i / DOUT, d = i - r * DOUT;
            int b = b0 + r;
            if (b < NROWS) {
                float ir = sgi[r * 300 + d] + bih[d];
                float iz = sgi[r * 300 + 100 + d] + bih[100 + d];
                float inn = sgi[r * 300 + 200 + d] + bih[200 + d];
                float hr = sgh[r * 300 + d] + bhh[d];
                float hz = sgh[r * 300 + 100 + d] + bhh[100 + d];
                float hn = sgh[r * 300 + 200 + d] + bhh[200 + d];
                float rr = sigmoidf_(ir + hr);
                float zz = sigmoidf_(iz + hz);
                float nn = tanhf(inn + rr * hn);
                float hnew = (1.0f - zz) * nn + zz * sh[i];
                sh[i] = hnew;
                g_membank[((size_t)b * WIND + s) * DOUT + d] = sx[i] + hnew;
            }
        }
        __syncthreads();
    }
}

// ---------------- Attention ----------------
__global__ void attn_kernel(float* __restrict__ attn_out)
{
    int gw = (blockIdx.x * blockDim.x + threadIdx.x) >> 5;
    int lane = threadIdx.x & 31;
    if (gw >= NROWS) return;
    const int b = gw;
    const float* __restrict__ mb = g_membank + (size_t)b * WIND * DOUT;
    float e[4];
#pragma unroll
    for (int m = 0; m < 4; m++) {
        int d = lane + 32 * m;
        e[m] = (d < DOUT) ? g_sutt[(b + 1) * DOUT + d] : 0.0f;
    }
    for (int hop = 0; hop < HOPS; hop++) {
        float lg[WIND];
#pragma unroll
        for (int k = 0; k < WIND; k++) {
            float p = 0.0f;
#pragma unroll
            for (int m = 0; m < 4; m++) {
                int d = lane + 32 * m;
                if (d < DOUT) p = fmaf(e[m], mb[k * DOUT + d], p);
            }
#pragma unroll
            for (int off = 16; off > 0; off >>= 1) p += __shfl_xor_sync(0xffffffffu, p, off);
            lg[k] = (b + k - (WIND - 1) >= 0) ? p : -1e10f;
        }
        float mx = lg[0];
#pragma unroll
        for (int k = 1; k < WIND; k++) mx = fmaxf(mx, lg[k]);
        float w[WIND], den = 0.0f;
#pragma unroll
        for (int k = 0; k < WIND; k++) { w[k] = expf(lg[k] - mx); den += w[k]; }
        float inv = 1.0f / den;
#pragma unroll
        for (int k = 0; k < WIND; k++) w[k] *= inv;
        if (lane < WIND) attn_out[((size_t)hop * NROWS + b) * WIND + lane] = w[lane];
#pragma unroll
        for (int m = 0; m < 4; m++) {
            int d = lane + 32 * m;
            if (d < DOUT) {
                float add = 0.0f;
#pragma unroll
                for (int k = 0; k < WIND; k++) add = fmaf(w[k], mb[k * DOUT + d], add);
                e[m] += add;
            }
        }
    }
#pragma unroll
    for (int m = 0; m < 4; m++) {
        int d = lane + 32 * m;
        if (d < DOUT) g_eps[b * DOUT + d] = e[m];
    }
}

// ---------------- Classifier ----------------
__global__ void cls_kernel(const float* __restrict__ cls_w, const float* __restrict__ cls_b,
                           float* __restrict__ pred)
{
    int gw = (blockIdx.x * blockDim.x + threadIdx.x) >> 5;
    int lane = threadIdx.x & 31;
    if (gw >= N_UTTS) return;
    const int n = gw;
    const float* __restrict__ s = (n == 0) ? g_sutt : (g_eps + (size_t)(n - 1) * DOUT);
    float z[NCLS];
#pragma unroll
    for (int c = 0; c < NCLS; c++) z[c] = 0.0f;
    for (int d = lane; d < DOUT; d += 32) {
        float sv = s[d];
#pragma unroll
        for (int c = 0; c < NCLS; c++) z[c] = fmaf(sv, cls_w[c * DOUT + d], z[c]);
    }
#pragma unroll
    for (int c = 0; c < NCLS; c++) {
#pragma unroll
        for (int off = 16; off > 0; off >>= 1) z[c] += __shfl_xor_sync(0xffffffffu, z[c], off);
        z[c] += cls_b[c];
    }
    float mx = z[0];
#pragma unroll
    for (int c = 1; c < NCLS; c++) mx = fmaxf(mx, z[c]);
    float den = 0.0f;
#pragma unroll
    for (int c = 0; c < NCLS; c++) den += expf(z[c] - mx);
    float lse = logf(den);
    if (lane < NCLS) pred[(size_t)n * NCLS + lane] = z[lane] - mx - lse;
}

extern "C" void kernel_launch(void* const* d_in, const int* in_sizes, int n_in,
                              void* d_out, int out_size) {
    const int*   sents   = (const int*)  d_in[0];
    const float* emb     = (const float*)d_in[2];
    const float* trans_w = (const float*)d_in[3];
    const float* trans_b = (const float*)d_in[4];
    const float* gru_wih = (const float*)d_in[5];
    const float* gru_whh = (const float*)d_in[6];
    const float* gru_bih = (const float*)d_in[7];
    const float* gru_bhh = (const float*)d_in[8];
    const float* cls_w   = (const float*)d_in[9];
    const float* cls_b   = (const float*)d_in[10];
    const float* w3      = (const float*)d_in[11];
    const float* b3      = (const float*)d_in[12];
    const float* w4      = (const float*)d_in[13];
    const float* b4      = (const float*)d_in[14];
    const float* w5      = (const float*)d_in[15];
    const float* b5      = (const float*)d_in[16];

    float* pred = (float*)d_out;
    float* attn = (float*)d_out + (size_t)N_UTTS * NCLS;

    static int once = 0;
    if (!once) {
        cudaFuncSetAttribute(conv_mma_kernel, cudaFuncAttributeMaxDynamicSharedMemorySize, CONV_SMEM);
        once = 1;
    }

    transpose_gru_kernel<<<(30000 + 255) / 256, 256>>>(gru_wih, gru_whh);
    prep_e_kernel<<<NPAIRS, 256>>>(sents, emb);
    prep_b_kernel<<<(NCHUNKS * 6144 + 255) / 256, 256>>>(w3, w4, w5);
    conv_mma_kernel<<<NPAIRS, 256, CONV_SMEM>>>(b3, b4, b5, trans_w, trans_b);
    gru_kernel<<<(NROWS + GRU_ROWS - 1) / GRU_ROWS, 320>>>(gru_bih, gru_bhh);
    attn_kernel<<<(NROWS * 32 + 127) / 128, 128>>>(attn);
    cls_kernel<<<(N_UTTS * 32 + 127) / 128, 128>>>(cls_w, cls_b, pred);
}